// round 13
// baseline (speedup 1.0000x reference)
#include <cuda_runtime.h>
#include <cuda_bf16.h>
#include <stdint.h>

// ============================================================================
// LocalGNNBranch: 3-layer GraphSAGE, N=100k, E=1.6M, D=64, B=64. All fp32.
//  - CSR: hist -> decoupled-lookback scan -> fill(+stateclr)
//  - DIAGNOSTIC k_gemm at launch idx 3 (ncu captures idx 3) — deterministic,
//    output fully overwritten by the real layer-0 GEMM.
//  - 3x [gather-mean agg (MLP=8, packed f32x2) -> FFMA2 GEMM v3]
//  - sum-pool readout
// ============================================================================

#define MAXN 100000
#define MAXE 1600000
#define DF   64
#define KK   128         // GEMM K = 2*DF (mean || x)
#define NT   128         // nodes per GEMM block
#define WS   66          // w_s k-row stride (floats)
#define ZS2  130         // z_s k-row stride (floats)
#define SCAN_CHUNK 1024
#define MAXBLK 128

typedef unsigned long long ull;

// ---- static device scratch ----
__device__ float g_mean[(size_t)MAXN * DF];
__device__ float g_h1[(size_t)MAXN * DF];
__device__ float g_h2[(size_t)MAXN * DF];
__device__ int   g_deg[MAXN];
__device__ int   g_rowstart[MAXN + 1];
__device__ int   g_cursor[MAXN];
__device__ int   g_csr[MAXE];
__device__ ull   g_scanstate[MAXBLK];

// ---- helpers ----
__device__ __forceinline__ ull pk2(float lo, float hi) {
    ull r; asm("mov.b64 %0, {%1, %2};" : "=l"(r) : "f"(lo), "f"(hi)); return r;
}
__device__ __forceinline__ void fma2(ull& d, ull a, ull b) {
    asm("fma.rn.f32x2 %0, %1, %2, %0;" : "+l"(d) : "l"(a), "l"(b));
}
__device__ __forceinline__ void add2(ull& d, ull a) {
    asm("add.rn.f32x2 %0, %0, %1;" : "+l"(d) : "l"(a));
}
__device__ __forceinline__ void mul2(ull& d, ull a) {
    asm("mul.rn.f32x2 %0, %0, %1;" : "+l"(d) : "l"(a));
}
__device__ __forceinline__ float2 up2(ull v) {
    float2 f; asm("mov.b64 {%0, %1}, %2;" : "=f"(f.x), "=f"(f.y) : "l"(v)); return f;
}
__device__ __forceinline__ void st_rel(ull* p, ull v) {
    asm volatile("st.global.release.gpu.u64 [%0], %1;" :: "l"(p), "l"(v) : "memory");
}
__device__ __forceinline__ ull ld_acq(const ull* p) {
    ull v; asm volatile("ld.global.acquire.gpu.u64 %0, [%1];" : "=l"(v) : "l"(p) : "memory");
    return v;
}

// ---------------------------------------------------------------------------
__global__ void k_hist(const int* __restrict__ dst, int e) {
    int i = blockIdx.x * blockDim.x + threadIdx.x;
    if (i < e) atomicAdd(&g_deg[dst[i]], 1);
}

__global__ __launch_bounds__(256) void k_scan(int n, int nblk) {
    __shared__ int s[256];
    __shared__ int s_prefix;
    int b = blockIdx.x, tid = threadIdx.x;
    int base = b * SCAN_CHUNK + tid * 4;
    int v[4];
    int tsum = 0;
#pragma unroll
    for (int i = 0; i < 4; i++) {
        int gi = base + i;
        v[i] = (gi < n) ? g_deg[gi] : 0;
        tsum += v[i];
    }
    s[tid] = tsum;
    __syncthreads();
    for (int d = 1; d < 256; d <<= 1) {
        int t = (tid >= d) ? s[tid - d] : 0;
        __syncthreads();
        s[tid] += t;
        __syncthreads();
    }
    int total = s[255];
    if (tid == 0) {
        st_rel(&g_scanstate[b], ((ull)total << 2) | 1ull);
        ull prefix = 0;
        int j = b - 1;
        while (j >= 0) {
            ull st = ld_acq(&g_scanstate[j]);
            ull f = st & 3ull;
            if (f == 0) continue;
            prefix += st >> 2;
            if (f == 2) break;
            j--;
        }
        st_rel(&g_scanstate[b], ((prefix + (ull)total) << 2) | 2ull);
        s_prefix = (int)prefix;
    }
    __syncthreads();
    int run = s_prefix + s[tid] - tsum;
#pragma unroll
    for (int i = 0; i < 4; i++) {
        int gi = base + i;
        if (gi < n) {
            g_rowstart[gi] = run;
            g_cursor[gi] = run;
            g_deg[gi] = 0;
            run += v[i];
        }
    }
    if (b == nblk - 1 && tid == 255) g_rowstart[n] = s_prefix + total;
}

__global__ void k_fill(const int* __restrict__ src, const int* __restrict__ dst, int e) {
    if (blockIdx.x == 0 && threadIdx.x < MAXBLK) g_scanstate[threadIdx.x] = 0;
    int i = blockIdx.x * blockDim.x + threadIdx.x;
    if (i < e) {
        int d = dst[i];
        int p = atomicAdd(&g_cursor[d], 1);
        g_csr[p] = src[i];
    }
}

// ---------------------------------------------------------------------------
// Aggregation (R12): 16 threads/node, LDG.128 as ulonglong2, MLP=8, packed adds.
__global__ __launch_bounds__(256) void k_agg(const float* __restrict__ x,
                                             float* __restrict__ meanout, int n) {
    int t = blockIdx.x * blockDim.x + threadIdx.x;
    int node = t >> 4;
    int c = t & 15;
    if (node >= n) return;
    int base = g_rowstart[node];
    int dg = g_rowstart[node + 1] - base;
    const ulonglong2* xv = (const ulonglong2*)x;
    const int* cp = g_csr + base;
    ull A0l = pk2(0.f, 0.f), A0h = A0l;
    ull A1l = A0l, A1h = A0l, A2l = A0l, A2h = A0l, A3l = A0l, A3h = A0l;
    int k = 0;
    for (; k + 8 <= dg; k += 8) {
        int s0 = __ldg(cp + k + 0) * 16 + c;
        int s1 = __ldg(cp + k + 1) * 16 + c;
        int s2 = __ldg(cp + k + 2) * 16 + c;
        int s3 = __ldg(cp + k + 3) * 16 + c;
        int s4 = __ldg(cp + k + 4) * 16 + c;
        int s5 = __ldg(cp + k + 5) * 16 + c;
        int s6 = __ldg(cp + k + 6) * 16 + c;
        int s7 = __ldg(cp + k + 7) * 16 + c;
        ulonglong2 v0 = __ldg(xv + s0);
        ulonglong2 v1 = __ldg(xv + s1);
        ulonglong2 v2 = __ldg(xv + s2);
        ulonglong2 v3 = __ldg(xv + s3);
        ulonglong2 v4 = __ldg(xv + s4);
        ulonglong2 v5 = __ldg(xv + s5);
        ulonglong2 v6 = __ldg(xv + s6);
        ulonglong2 v7 = __ldg(xv + s7);
        add2(A0l, v0.x); add2(A0h, v0.y);
        add2(A1l, v1.x); add2(A1h, v1.y);
        add2(A2l, v2.x); add2(A2h, v2.y);
        add2(A3l, v3.x); add2(A3h, v3.y);
        add2(A0l, v4.x); add2(A0h, v4.y);
        add2(A1l, v5.x); add2(A1h, v5.y);
        add2(A2l, v6.x); add2(A2h, v6.y);
        add2(A3l, v7.x); add2(A3h, v7.y);
    }
    for (; k + 4 <= dg; k += 4) {
        int s0 = __ldg(cp + k + 0) * 16 + c;
        int s1 = __ldg(cp + k + 1) * 16 + c;
        int s2 = __ldg(cp + k + 2) * 16 + c;
        int s3 = __ldg(cp + k + 3) * 16 + c;
        ulonglong2 v0 = __ldg(xv + s0);
        ulonglong2 v1 = __ldg(xv + s1);
        ulonglong2 v2 = __ldg(xv + s2);
        ulonglong2 v3 = __ldg(xv + s3);
        add2(A0l, v0.x); add2(A0h, v0.y);
        add2(A1l, v1.x); add2(A1h, v1.y);
        add2(A2l, v2.x); add2(A2h, v2.y);
        add2(A3l, v3.x); add2(A3h, v3.y);
    }
    for (; k < dg; k++) {
        int s = __ldg(cp + k) * 16 + c;
        ulonglong2 v = __ldg(xv + s);
        add2(A0l, v.x); add2(A0h, v.y);
    }
    add2(A0l, A1l); add2(A2l, A3l); add2(A0l, A2l);
    add2(A0h, A1h); add2(A2h, A3h); add2(A0h, A2h);
    float invd = 1.0f / (float)max(dg, 1);
    ull iv = pk2(invd, invd);
    mul2(A0l, iv); mul2(A0h, iv);
    ulonglong2 outv; outv.x = A0l; outv.y = A0h;
    ((ulonglong2*)meanout)[node * 16 + c] = outv;
}

// ---------------------------------------------------------------------------
// GEMM v3 (R8-proven): out = relu(l2norm([mean||x] @ [Wl;Wr]^T + bl))
__global__ __launch_bounds__(256, 2) void k_gemm(const float* __restrict__ mean,
                                                 const float* __restrict__ xin,
                                                 const float* __restrict__ Wl,
                                                 const float* __restrict__ bl,
                                                 const float* __restrict__ Wr,
                                                 float* __restrict__ out, int n) {
    extern __shared__ float smem[];
    float* w_s = smem;               // [KK][WS]
    float* z_s = smem + KK * WS;     // [KK][ZS2], z[k][node]
    int tid = threadIdx.x;

    for (int i = tid; i < DF * DF; i += 256) {
        int o = i >> 6, k = i & 63;
        int pos = (((o & 7) >> 1) << 4) + ((o >> 3) << 1) + (o & 1);
        w_s[k * WS + pos]        = Wl[i];
        w_s[(k + DF) * WS + pos] = Wr[i];
    }

    int nodeBase = blockIdx.x * NT;
    {
        int nl_lo = tid & 7;
        int cq    = (tid >> 3) & 31;
#pragma unroll 4
        for (int it = 0; it < 16; it++) {
            int nl = it * 8 + nl_lo;
            int gn = nodeBase + nl;
            float4 v = make_float4(0.f, 0.f, 0.f, 0.f);
            if (gn < n) {
                const float4* p = (cq < 16)
                    ? ((const float4*)(mean + (size_t)gn * DF) + cq)
                    : ((const float4*)(xin + (size_t)gn * DF) + (cq - 16));
                v = __ldg(p);
            }
            int k0 = cq * 4;
            z_s[(k0 + 0) * ZS2 + nl] = v.x;
            z_s[(k0 + 1) * ZS2 + nl] = v.y;
            z_s[(k0 + 2) * ZS2 + nl] = v.z;
            z_s[(k0 + 3) * ZS2 + nl] = v.w;
        }
    }
    __syncthreads();

    int og = tid & 7;
    int ng = tid >> 3;
    int n0 = ng * 4;

    ull acc[4][4];
    {
        const ull* bp = (const ull*)(bl + og * 8);
        ull b0 = bp[0], b1 = bp[1], b2 = bp[2], b3 = bp[3];
#pragma unroll
        for (int nn = 0; nn < 4; nn++) {
            acc[nn][0] = b0; acc[nn][1] = b1; acc[nn][2] = b2; acc[nn][3] = b3;
        }
    }

#pragma unroll 4
    for (int k = 0; k < KK; k++) {
        const float* zr = z_s + k * ZS2 + n0;
        float za = zr[0], zb = zr[1], zc = zr[2], zd = zr[3];
        ull z0 = pk2(za, za);
        ull z1 = pk2(zb, zb);
        ull z2 = pk2(zc, zc);
        ull z3 = pk2(zd, zd);
        const float* wr_ = w_s + k * WS + og * 2;
        ull w0 = *(const ull*)(wr_ + 0);
        ull w1 = *(const ull*)(wr_ + 16);
        ull w2 = *(const ull*)(wr_ + 32);
        ull w3 = *(const ull*)(wr_ + 48);
        fma2(acc[0][0], z0, w0); fma2(acc[0][1], z0, w1);
        fma2(acc[0][2], z0, w2); fma2(acc[0][3], z0, w3);
        fma2(acc[1][0], z1, w0); fma2(acc[1][1], z1, w1);
        fma2(acc[1][2], z1, w2); fma2(acc[1][3], z1, w3);
        fma2(acc[2][0], z2, w0); fma2(acc[2][1], z2, w1);
        fma2(acc[2][2], z2, w2); fma2(acc[2][3], z2, w3);
        fma2(acc[3][0], z3, w0); fma2(acc[3][1], z3, w1);
        fma2(acc[3][2], z3, w2); fma2(acc[3][3], z3, w3);
    }

#pragma unroll
    for (int nn = 0; nn < 4; nn++) {
        ull sq2 = pk2(0.f, 0.f);
#pragma unroll
        for (int p = 0; p < 4; p++) fma2(sq2, acc[nn][p], acc[nn][p]);
        float2 sf = up2(sq2);
        float sq = sf.x + sf.y;
        sq += __shfl_xor_sync(0xffffffffu, sq, 1);
        sq += __shfl_xor_sync(0xffffffffu, sq, 2);
        sq += __shfl_xor_sync(0xffffffffu, sq, 4);
        float scale = 1.0f / fmaxf(sqrtf(sq), 1e-12f);
        int node = nodeBase + n0 + nn;
        if (node < n) {
            float2 f0 = up2(acc[nn][0]), f1 = up2(acc[nn][1]);
            float2 f2 = up2(acc[nn][2]), f3 = up2(acc[nn][3]);
            float4 o0 = make_float4(fmaxf(f0.x * scale, 0.f), fmaxf(f0.y * scale, 0.f),
                                    fmaxf(f1.x * scale, 0.f), fmaxf(f1.y * scale, 0.f));
            float4 o1 = make_float4(fmaxf(f2.x * scale, 0.f), fmaxf(f2.y * scale, 0.f),
                                    fmaxf(f3.x * scale, 0.f), fmaxf(f3.y * scale, 0.f));
            float4* op = (float4*)(out + (size_t)node * DF + og * 8);
            op[0] = o0; op[1] = o1;
        }
    }
}

// ---------------------------------------------------------------------------
__device__ __forceinline__ int lower_bound_i(const int* __restrict__ a, int n, int v) {
    int lo = 0, hi = n;
    while (lo < hi) {
        int m = (lo + hi) >> 1;
        if (a[m] < v) lo = m + 1; else hi = m;
    }
    return lo;
}

__global__ __launch_bounds__(256) void k_pool(const float* __restrict__ h,
                                              const int* __restrict__ batch,
                                              float* __restrict__ out, int n) {
    __shared__ int s_lo, s_hi;
    __shared__ float red[4][DF];
    int b = blockIdx.x;
    if (threadIdx.x == 0) {
        s_lo = lower_bound_i(batch, n, b);
        s_hi = lower_bound_i(batch, n, b + 1);
    }
    __syncthreads();
    int lo = s_lo, hi = s_hi;
    int f = threadIdx.x & 63;
    int lane = threadIdx.x >> 6;
    float acc = 0.f;
    for (int nd = lo + lane; nd < hi; nd += 4)
        acc += h[(size_t)nd * DF + f];
    red[lane][f] = acc;
    __syncthreads();
    if (lane == 0)
        out[b * DF + f] = red[0][f] + red[1][f] + red[2][f] + red[3][f];
}

// ---------------------------------------------------------------------------
extern "C" void kernel_launch(void* const* d_in, const int* in_sizes, int n_in,
                              void* d_out, int out_size) {
    const float* x_raw = (const float*)d_in[0];
    const int*   ei    = (const int*)d_in[1];
    const int*   batch = (const int*)d_in[2];
    const float* W[9];
    for (int i = 0; i < 9; i++) W[i] = (const float*)d_in[3 + i];

    int n = in_sizes[0] / DF;
    int e = in_sizes[1] / 2;
    int b = out_size / DF;
    const int* src = ei;
    const int* dst = ei + e;
    float* out = (float*)d_out;

    int nblk = (n + SCAN_CHUNK - 1) / SCAN_CHUNK;   // 98

    static int smem_set = 0;
    const int GEMM_SMEM = (KK * WS + KK * ZS2) * 4;   // 100,352 bytes
    if (!smem_set) {
        cudaFuncSetAttribute(k_gemm, cudaFuncAttributeMaxDynamicSharedMemorySize,
                             GEMM_SMEM);
        smem_set = 1;
    }

    // ---- CSR build ----
    k_hist<<<(e + 255) / 256, 256>>>(dst, e);          // 0
    k_scan<<<nblk, 256>>>(n, nblk);                    // 1
    k_fill<<<(e + 255) / 256, 256>>>(src, dst, e);     // 2

    float* mean; cudaGetSymbolAddress((void**)&mean, g_mean);
    float* h1;   cudaGetSymbolAddress((void**)&h1, g_h1);
    float* h2;   cudaGetSymbolAddress((void**)&h2, g_h2);

    int aggGrid  = (n * 16 + 255) / 256;
    int gemmGrid = (n + NT - 1) / NT;

    // DIAGNOSTIC (idx 3, ncu captures this): production-config GEMM on
    // deterministic inputs (x_raw twice); h1 is fully overwritten by the
    // real layer-0 GEMM below, so final output is unaffected.
    k_gemm<<<gemmGrid, 256, GEMM_SMEM>>>(x_raw, x_raw, W[0], W[1], W[2], h1, n);  // 3 <- ncu

    k_agg<<<aggGrid, 256>>>(x_raw, mean, n);                                     // 4
    k_gemm<<<gemmGrid, 256, GEMM_SMEM>>>(mean, x_raw, W[0], W[1], W[2], h1, n);  // 5
    k_agg<<<aggGrid, 256>>>(h1, mean, n);
    k_gemm<<<gemmGrid, 256, GEMM_SMEM>>>(mean, h1, W[3], W[4], W[5], h2, n);
    k_agg<<<aggGrid, 256>>>(h2, mean, n);
    k_gemm<<<gemmGrid, 256, GEMM_SMEM>>>(mean, h2, W[6], W[7], W[8], h1, n);

    k_pool<<<b, 256>>>(h1, batch, out, n);
}

// round 15
// speedup vs baseline: 1.1702x; 1.1702x over previous
#include <cuda_runtime.h>
#include <cuda_bf16.h>
#include <stdint.h>

// ============================================================================
// LocalGNNBranch: 3-layer GraphSAGE, N=100k, E=1.6M, D=64, B=64. All fp32.
//  - CSR: hist -> decoupled-lookback scan -> fill(+stateclr)
//  - 3x [gather-mean agg (MLP=8, packed f32x2) -> FFMA2 GEMM v4]
//  - sum-pool readout
// GEMM v4: 128 threads, 128 nodes x 64 outs/block; thread = 8 nodes x 8 outs,
//   acc packed over NODE pairs. Per k: 4 LDS.64 z (node pairs, conflict-free)
//   + 8 scalar w broadcasts (interleaved layout, conflict-free) + 8 movs
//   -> 12 LDS / 32 FFMA2  (R8 was 8 LDS / 16 FFMA2). FMA-pipe-bound on paper.
// ============================================================================

#define MAXN 100000
#define MAXE 1600000
#define DF   64
#define KK   128         // GEMM K = 2*DF (mean || x)
#define NT   128         // nodes per GEMM block
#define WS   66          // w_s k-row stride (floats)
#define ZS2  130         // z_s k-row stride (floats)
#define SCAN_CHUNK 1024
#define MAXBLK 128

typedef unsigned long long ull;

// ---- static device scratch ----
__device__ float g_mean[(size_t)MAXN * DF];
__device__ float g_h1[(size_t)MAXN * DF];
__device__ float g_h2[(size_t)MAXN * DF];
__device__ int   g_deg[MAXN];
__device__ int   g_rowstart[MAXN + 1];
__device__ int   g_cursor[MAXN];
__device__ int   g_csr[MAXE];
__device__ ull   g_scanstate[MAXBLK];

// ---- helpers ----
__device__ __forceinline__ ull pk2(float lo, float hi) {
    ull r; asm("mov.b64 %0, {%1, %2};" : "=l"(r) : "f"(lo), "f"(hi)); return r;
}
__device__ __forceinline__ void fma2(ull& d, ull a, ull b) {
    asm("fma.rn.f32x2 %0, %1, %2, %0;" : "+l"(d) : "l"(a), "l"(b));
}
__device__ __forceinline__ void add2(ull& d, ull a) {
    asm("add.rn.f32x2 %0, %0, %1;" : "+l"(d) : "l"(a));
}
__device__ __forceinline__ void mul2(ull& d, ull a) {
    asm("mul.rn.f32x2 %0, %0, %1;" : "+l"(d) : "l"(a));
}
__device__ __forceinline__ float2 up2(ull v) {
    float2 f; asm("mov.b64 {%0, %1}, %2;" : "=f"(f.x), "=f"(f.y) : "l"(v)); return f;
}
__device__ __forceinline__ void st_rel(ull* p, ull v) {
    asm volatile("st.global.release.gpu.u64 [%0], %1;" :: "l"(p), "l"(v) : "memory");
}
__device__ __forceinline__ ull ld_acq(const ull* p) {
    ull v; asm volatile("ld.global.acquire.gpu.u64 %0, [%1];" : "=l"(v) : "l"(p) : "memory");
    return v;
}

// ---------------------------------------------------------------------------
__global__ void k_hist(const int* __restrict__ dst, int e) {
    int i = blockIdx.x * blockDim.x + threadIdx.x;
    if (i < e) atomicAdd(&g_deg[dst[i]], 1);
}

__global__ __launch_bounds__(256) void k_scan(int n, int nblk) {
    __shared__ int s[256];
    __shared__ int s_prefix;
    int b = blockIdx.x, tid = threadIdx.x;
    int base = b * SCAN_CHUNK + tid * 4;
    int v[4];
    int tsum = 0;
#pragma unroll
    for (int i = 0; i < 4; i++) {
        int gi = base + i;
        v[i] = (gi < n) ? g_deg[gi] : 0;
        tsum += v[i];
    }
    s[tid] = tsum;
    __syncthreads();
    for (int d = 1; d < 256; d <<= 1) {
        int t = (tid >= d) ? s[tid - d] : 0;
        __syncthreads();
        s[tid] += t;
        __syncthreads();
    }
    int total = s[255];
    if (tid == 0) {
        st_rel(&g_scanstate[b], ((ull)total << 2) | 1ull);
        ull prefix = 0;
        int j = b - 1;
        while (j >= 0) {
            ull st = ld_acq(&g_scanstate[j]);
            ull f = st & 3ull;
            if (f == 0) continue;
            prefix += st >> 2;
            if (f == 2) break;
            j--;
        }
        st_rel(&g_scanstate[b], ((prefix + (ull)total) << 2) | 2ull);
        s_prefix = (int)prefix;
    }
    __syncthreads();
    int run = s_prefix + s[tid] - tsum;
#pragma unroll
    for (int i = 0; i < 4; i++) {
        int gi = base + i;
        if (gi < n) {
            g_rowstart[gi] = run;
            g_cursor[gi] = run;
            g_deg[gi] = 0;
            run += v[i];
        }
    }
    if (b == nblk - 1 && tid == 255) g_rowstart[n] = s_prefix + total;
}

__global__ void k_fill(const int* __restrict__ src, const int* __restrict__ dst, int e) {
    if (blockIdx.x == 0 && threadIdx.x < MAXBLK) g_scanstate[threadIdx.x] = 0;
    int i = blockIdx.x * blockDim.x + threadIdx.x;
    if (i < e) {
        int d = dst[i];
        int p = atomicAdd(&g_cursor[d], 1);
        g_csr[p] = src[i];
    }
}

// ---------------------------------------------------------------------------
// Aggregation (R12): 16 threads/node, LDG.128 as ulonglong2, MLP=8, packed adds.
__global__ __launch_bounds__(256) void k_agg(const float* __restrict__ x,
                                             float* __restrict__ meanout, int n) {
    int t = blockIdx.x * blockDim.x + threadIdx.x;
    int node = t >> 4;
    int c = t & 15;
    if (node >= n) return;
    int base = g_rowstart[node];
    int dg = g_rowstart[node + 1] - base;
    const ulonglong2* xv = (const ulonglong2*)x;
    const int* cp = g_csr + base;
    ull A0l = pk2(0.f, 0.f), A0h = A0l;
    ull A1l = A0l, A1h = A0l, A2l = A0l, A2h = A0l, A3l = A0l, A3h = A0l;
    int k = 0;
    for (; k + 8 <= dg; k += 8) {
        int s0 = __ldg(cp + k + 0) * 16 + c;
        int s1 = __ldg(cp + k + 1) * 16 + c;
        int s2 = __ldg(cp + k + 2) * 16 + c;
        int s3 = __ldg(cp + k + 3) * 16 + c;
        int s4 = __ldg(cp + k + 4) * 16 + c;
        int s5 = __ldg(cp + k + 5) * 16 + c;
        int s6 = __ldg(cp + k + 6) * 16 + c;
        int s7 = __ldg(cp + k + 7) * 16 + c;
        ulonglong2 v0 = __ldg(xv + s0);
        ulonglong2 v1 = __ldg(xv + s1);
        ulonglong2 v2 = __ldg(xv + s2);
        ulonglong2 v3 = __ldg(xv + s3);
        ulonglong2 v4 = __ldg(xv + s4);
        ulonglong2 v5 = __ldg(xv + s5);
        ulonglong2 v6 = __ldg(xv + s6);
        ulonglong2 v7 = __ldg(xv + s7);
        add2(A0l, v0.x); add2(A0h, v0.y);
        add2(A1l, v1.x); add2(A1h, v1.y);
        add2(A2l, v2.x); add2(A2h, v2.y);
        add2(A3l, v3.x); add2(A3h, v3.y);
        add2(A0l, v4.x); add2(A0h, v4.y);
        add2(A1l, v5.x); add2(A1h, v5.y);
        add2(A2l, v6.x); add2(A2h, v6.y);
        add2(A3l, v7.x); add2(A3h, v7.y);
    }
    for (; k + 4 <= dg; k += 4) {
        int s0 = __ldg(cp + k + 0) * 16 + c;
        int s1 = __ldg(cp + k + 1) * 16 + c;
        int s2 = __ldg(cp + k + 2) * 16 + c;
        int s3 = __ldg(cp + k + 3) * 16 + c;
        ulonglong2 v0 = __ldg(xv + s0);
        ulonglong2 v1 = __ldg(xv + s1);
        ulonglong2 v2 = __ldg(xv + s2);
        ulonglong2 v3 = __ldg(xv + s3);
        add2(A0l, v0.x); add2(A0h, v0.y);
        add2(A1l, v1.x); add2(A1h, v1.y);
        add2(A2l, v2.x); add2(A2h, v2.y);
        add2(A3l, v3.x); add2(A3h, v3.y);
    }
    for (; k < dg; k++) {
        int s = __ldg(cp + k) * 16 + c;
        ulonglong2 v = __ldg(xv + s);
        add2(A0l, v.x); add2(A0h, v.y);
    }
    add2(A0l, A1l); add2(A2l, A3l); add2(A0l, A2l);
    add2(A0h, A1h); add2(A2h, A3h); add2(A0h, A2h);
    float invd = 1.0f / (float)max(dg, 1);
    ull iv = pk2(invd, invd);
    mul2(A0l, iv); mul2(A0h, iv);
    ulonglong2 outv; outv.x = A0l; outv.y = A0h;
    ((ulonglong2*)meanout)[node * 16 + c] = outv;
}

// ---------------------------------------------------------------------------
// GEMM v4: out = relu(l2norm([mean||x] @ [Wl;Wr]^T + bl))
// 128 threads, 128 nodes x 64 outs/block; thread = 8 nodes (4 pairs) x 8 outs.
// og = tid&7 (outs og*8..og*8+7), ng = tid>>3 (nodes ng*8..ng*8+7).
__global__ __launch_bounds__(128, 2) void k_gemm(const float* __restrict__ mean,
                                                 const float* __restrict__ xin,
                                                 const float* __restrict__ Wl,
                                                 const float* __restrict__ bl,
                                                 const float* __restrict__ Wr,
                                                 float* __restrict__ out, int n) {
    extern __shared__ float smem[];
    float* w_s = smem;               // [KK][WS], w at pos(o) = (o&7)*8 + (o>>3)
    float* z_s = smem + KK * WS;     // [KK][ZS2], z[k][node]
    int tid = threadIdx.x;

    // weights interleaved: pos(o) = (o&7)*8 + (o>>3)
    for (int i = tid; i < DF * DF; i += 128) {
        int o = i >> 6, k = i & 63;
        int pos = ((o & 7) << 3) + (o >> 3);
        w_s[k * WS + pos]        = Wl[i];
        w_s[(k + DF) * WS + pos] = Wr[i];
    }

    int nodeBase = blockIdx.x * NT;
    // z transpose: warp covers 8 nodes x 4 k-quads; banks 8*cq+2*i2+nl distinct.
    {
        int nl_lo = tid & 7;
        int cq_lo = (tid >> 3) & 15;   // 0..15
#pragma unroll
        for (int h = 0; h < 2; h++) {
            int cq = cq_lo + h * 16;   // 0..31
#pragma unroll 4
            for (int it = 0; it < 16; it++) {
                int nl = it * 8 + nl_lo;
                int gn = nodeBase + nl;
                float4 v = make_float4(0.f, 0.f, 0.f, 0.f);
                if (gn < n) {
                    const float4* p = (cq < 16)
                        ? ((const float4*)(mean + (size_t)gn * DF) + cq)
                        : ((const float4*)(xin + (size_t)gn * DF) + (cq - 16));
                    v = __ldg(p);
                }
                int k0 = cq * 4;
                z_s[(k0 + 0) * ZS2 + nl] = v.x;
                z_s[(k0 + 1) * ZS2 + nl] = v.y;
                z_s[(k0 + 2) * ZS2 + nl] = v.z;
                z_s[(k0 + 3) * ZS2 + nl] = v.w;
            }
        }
    }
    __syncthreads();

    int og = tid & 7;        // outs og*8+j
    int ng = tid >> 3;       // 0..15 -> nodes ng*8 .. ng*8+7
    int n0 = ng * 8;         // <= 120

    // acc[p][j] = (out og*8+j of node n0+2p, same out of node n0+2p+1)
    ull acc[4][8];
#pragma unroll
    for (int j = 0; j < 8; j++) {
        float bv = bl[og * 8 + j];
        ull bb = pk2(bv, bv);
#pragma unroll
        for (int p = 0; p < 4; p++) acc[p][j] = bb;
    }

#pragma unroll 4
    for (int k = 0; k < KK; k++) {
        const float* zr = z_s + k * ZS2 + n0;
        ull z0 = *(const ull*)(zr + 0);
        ull z1 = *(const ull*)(zr + 2);
        ull z2 = *(const ull*)(zr + 4);
        ull z3 = *(const ull*)(zr + 6);
        const float* wr_ = w_s + k * WS + og * 8;   // pos(og*8+j) = j*8+og? no:
        // pos(o)= (o&7)*8+(o>>3); o=og*8+j -> o&7=j, o>>3=og -> pos = j*8+og
#pragma unroll
        for (int j = 0; j < 8; j++) {
            float wv = w_s[k * WS + j * 8 + og];
            ull w = pk2(wv, wv);
            fma2(acc[0][j], z0, w);
            fma2(acc[1][j], z1, w);
            fma2(acc[2][j], z2, w);
            fma2(acc[3][j], z3, w);
        }
        (void)wr_;
    }

    // epilogue: per node-pair packed sq over 8 outs, reduce across og lanes.
#pragma unroll
    for (int p = 0; p < 4; p++) {
        ull sq2 = pk2(0.f, 0.f);
#pragma unroll
        for (int j = 0; j < 8; j++) fma2(sq2, acc[p][j], acc[p][j]);
        float2 sf = up2(sq2);
        float sqA = sf.x, sqB = sf.y;
        sqA += __shfl_xor_sync(0xffffffffu, sqA, 1);
        sqA += __shfl_xor_sync(0xffffffffu, sqA, 2);
        sqA += __shfl_xor_sync(0xffffffffu, sqA, 4);
        sqB += __shfl_xor_sync(0xffffffffu, sqB, 1);
        sqB += __shfl_xor_sync(0xffffffffu, sqB, 2);
        sqB += __shfl_xor_sync(0xffffffffu, sqB, 4);
        float scA = 1.0f / fmaxf(sqrtf(sqA), 1e-12f);
        float scB = 1.0f / fmaxf(sqrtf(sqB), 1e-12f);
        int nodeA = nodeBase + n0 + 2 * p;
        int nodeB = nodeA + 1;
        float fx[8], fy[8];
#pragma unroll
        for (int j = 0; j < 8; j++) {
            float2 f = up2(acc[p][j]);
            fx[j] = f.x; fy[j] = f.y;
        }
        if (nodeA < n) {
            float4 o0 = make_float4(fmaxf(fx[0] * scA, 0.f), fmaxf(fx[1] * scA, 0.f),
                                    fmaxf(fx[2] * scA, 0.f), fmaxf(fx[3] * scA, 0.f));
            float4 o1 = make_float4(fmaxf(fx[4] * scA, 0.f), fmaxf(fx[5] * scA, 0.f),
                                    fmaxf(fx[6] * scA, 0.f), fmaxf(fx[7] * scA, 0.f));
            float4* op = (float4*)(out + (size_t)nodeA * DF + og * 8);
            op[0] = o0; op[1] = o1;
        }
        if (nodeB < n) {
            float4 o0 = make_float4(fmaxf(fy[0] * scB, 0.f), fmaxf(fy[1] * scB, 0.f),
                                    fmaxf(fy[2] * scB, 0.f), fmaxf(fy[3] * scB, 0.f));
            float4 o1 = make_float4(fmaxf(fy[4] * scB, 0.f), fmaxf(fy[5] * scB, 0.f),
                                    fmaxf(fy[6] * scB, 0.f), fmaxf(fy[7] * scB, 0.f));
            float4* op = (float4*)(out + (size_t)nodeB * DF + og * 8);
            op[0] = o0; op[1] = o1;
        }
    }
}

// ---------------------------------------------------------------------------
__device__ __forceinline__ int lower_bound_i(const int* __restrict__ a, int n, int v) {
    int lo = 0, hi = n;
    while (lo < hi) {
        int m = (lo + hi) >> 1;
        if (a[m] < v) lo = m + 1; else hi = m;
    }
    return lo;
}

__global__ __launch_bounds__(256) void k_pool(const float* __restrict__ h,
                                              const int* __restrict__ batch,
                                              float* __restrict__ out, int n) {
    __shared__ int s_lo, s_hi;
    __shared__ float red[4][DF];
    int b = blockIdx.x;
    if (threadIdx.x == 0) {
        s_lo = lower_bound_i(batch, n, b);
        s_hi = lower_bound_i(batch, n, b + 1);
    }
    __syncthreads();
    int lo = s_lo, hi = s_hi;
    int f = threadIdx.x & 63;
    int lane = threadIdx.x >> 6;
    float acc = 0.f;
    for (int nd = lo + lane; nd < hi; nd += 4)
        acc += h[(size_t)nd * DF + f];
    red[lane][f] = acc;
    __syncthreads();
    if (lane == 0)
        out[b * DF + f] = red[0][f] + red[1][f] + red[2][f] + red[3][f];
}

// ---------------------------------------------------------------------------
extern "C" void kernel_launch(void* const* d_in, const int* in_sizes, int n_in,
                              void* d_out, int out_size) {
    const float* x_raw = (const float*)d_in[0];
    const int*   ei    = (const int*)d_in[1];
    const int*   batch = (const int*)d_in[2];
    const float* W[9];
    for (int i = 0; i < 9; i++) W[i] = (const float*)d_in[3 + i];

    int n = in_sizes[0] / DF;
    int e = in_sizes[1] / 2;
    int b = out_size / DF;
    const int* src = ei;
    const int* dst = ei + e;
    float* out = (float*)d_out;

    int nblk = (n + SCAN_CHUNK - 1) / SCAN_CHUNK;   // 98

    static int smem_set = 0;
    const int GEMM_SMEM = (KK * WS + KK * ZS2) * 4;   // 100,352 bytes
    if (!smem_set) {
        cudaFuncSetAttribute(k_gemm, cudaFuncAttributeMaxDynamicSharedMemorySize,
                             GEMM_SMEM);
        smem_set = 1;
    }

    // ---- CSR build ----
    k_hist<<<(e + 255) / 256, 256>>>(dst, e);          // 0
    k_scan<<<nblk, 256>>>(n, nblk);                    // 1
    k_fill<<<(e + 255) / 256, 256>>>(src, dst, e);     // 2

    float* mean; cudaGetSymbolAddress((void**)&mean, g_mean);
    float* h1;   cudaGetSymbolAddress((void**)&h1, g_h1);
    float* h2;   cudaGetSymbolAddress((void**)&h2, g_h2);

    int aggGrid  = (n * 16 + 255) / 256;
    int gemmGrid = (n + NT - 1) / NT;

    k_agg<<<aggGrid, 256>>>(x_raw, mean, n);                                     // 3 <- ncu
    k_gemm<<<gemmGrid, 128, GEMM_SMEM>>>(mean, x_raw, W[0], W[1], W[2], h1, n);  // 4
    k_agg<<<aggGrid, 256>>>(h1, mean, n);
    k_gemm<<<gemmGrid, 128, GEMM_SMEM>>>(mean, h1, W[3], W[4], W[5], h2, n);
    k_agg<<<aggGrid, 256>>>(h2, mean, n);
    k_gemm<<<gemmGrid, 128, GEMM_SMEM>>>(mean, h2, W[6], W[7], W[8], h1, n);

    k_pool<<<b, 256>>>(h1, batch, out, n);
}